// round 2
// baseline (speedup 1.0000x reference)
#include <cuda_runtime.h>
#include <math.h>

#define N_NODES 50000
#define N_EDGES 400000
#define E_TOT   450000
#define IN_CH   814
#define HID     128
#define HEADS1  4
#define D1      (HEADS1*HID)   /* 512 */
#define NUM_CLASSES 46
#define NUM_GRAPHS  64
#define NEG_SLOPE   0.2f

// ---------------- scratch (static device globals; no runtime alloc) --------
__device__ float g_h1[N_NODES * D1];        // x @ W1
__device__ float g_out1[N_NODES * D1];      // relu(GAT1 out)
__device__ float g_h2[N_NODES * HID];       // out1 @ W2
__device__ float g_out2[N_NODES * HID];     // relu(GAT2 out)
__device__ float g_als1[N_NODES * HEADS1];
__device__ float g_ald1[N_NODES * HEADS1];
__device__ float g_als2[N_NODES];
__device__ float g_ald2[N_NODES];
__device__ int   g_counts[N_NODES];
__device__ int   g_offsets[N_NODES + 1];
__device__ int   g_cursor[N_NODES];
__device__ int   g_src_sorted[E_TOT];
__device__ float g_alpha1[E_TOT * HEADS1];
__device__ float g_alpha2[E_TOT];
__device__ float g_pool[NUM_GRAPHS * HID];
__device__ int   g_cnt[NUM_GRAPHS];

// ---------------- helpers --------------------------------------------------
__device__ __forceinline__ float warpMax(float v) {
#pragma unroll
    for (int o = 16; o > 0; o >>= 1) v = fmaxf(v, __shfl_xor_sync(0xffffffffu, v, o));
    return v;
}
__device__ __forceinline__ float warpSum(float v) {
#pragma unroll
    for (int o = 16; o > 0; o >>= 1) v += __shfl_xor_sync(0xffffffffu, v, o);
    return v;
}
__device__ __forceinline__ float lrelu(float x) { return x > 0.f ? x : NEG_SLOPE * x; }

// ---------------- zero scratch ---------------------------------------------
__global__ void zero_kernel() {
    int i = blockIdx.x * blockDim.x + threadIdx.x;
    if (i < N_NODES) g_counts[i] = 0;
    if (i < NUM_GRAPHS * HID) g_pool[i] = 0.f;
    if (i < NUM_GRAPHS) g_cnt[i] = 0;
}

// ---------------- CSR build (dst-sorted) ------------------------------------
__global__ void hist_kernel(const int* __restrict__ ei) {
    int e = blockIdx.x * blockDim.x + threadIdx.x;
    if (e >= E_TOT) return;
    int dst = (e < N_EDGES) ? ei[N_EDGES + e] : (e - N_EDGES);
    atomicAdd(&g_counts[dst], 1);
}

__global__ void scan_kernel() {
    __shared__ int sh[1024];
    const int n = N_NODES;
    const int chunk = (n + 1023) / 1024;
    int tid = threadIdx.x;
    int b = tid * chunk;
    int e = b + chunk; if (e > n) e = n; if (b > n) b = n;
    int s = 0;
    for (int i = b; i < e; i++) s += g_counts[i];
    sh[tid] = s;
    __syncthreads();
    for (int o = 1; o < 1024; o <<= 1) {
        int v = 0;
        if (tid >= o) v = sh[tid - o];
        __syncthreads();
        if (tid >= o) sh[tid] += v;
        __syncthreads();
    }
    int run = (tid == 0) ? 0 : sh[tid - 1];
    for (int i = b; i < e; i++) {
        g_offsets[i] = run;
        g_cursor[i]  = run;
        run += g_counts[i];
    }
    if (tid == 1023) g_offsets[n] = sh[1023];
}

__global__ void scatter_kernel(const int* __restrict__ ei) {
    int e = blockIdx.x * blockDim.x + threadIdx.x;
    if (e >= E_TOT) return;
    int src, dst;
    if (e < N_EDGES) { src = ei[e]; dst = ei[N_EDGES + e]; }
    else             { src = e - N_EDGES; dst = src; }
    int pos = atomicAdd(&g_cursor[dst], 1);
    g_src_sorted[pos] = src;
}

// ---------------- fp32 SGEMM: C[M,N] = A[M,K] @ B[K,N] ----------------------
__global__ __launch_bounds__(256) void sgemm128(
    const float* __restrict__ A, const float* __restrict__ B,
    float* __restrict__ C, int M, int N, int K)
{
    __shared__ float As[8][128];
    __shared__ float Bs[8][128];
    int tid = threadIdx.x;
    int tx = tid & 15, ty = tid >> 4;
    int rowBase = blockIdx.y * 128;
    int colBase = blockIdx.x * 128;

    float acc[8][8];
#pragma unroll
    for (int i = 0; i < 8; i++)
#pragma unroll
        for (int j = 0; j < 8; j++) acc[i][j] = 0.f;

    for (int k0 = 0; k0 < K; k0 += 8) {
#pragma unroll
        for (int i = 0; i < 4; i++) {
            int idx = tid + 256 * i;
            int r = idx >> 3, c = idx & 7;
            int gr = rowBase + r, gc = k0 + c;
            As[c][r] = (gr < M && gc < K) ? A[(size_t)gr * K + gc] : 0.f;
        }
#pragma unroll
        for (int i = 0; i < 4; i++) {
            int idx = tid + 256 * i;
            int r = idx >> 7, c = idx & 127;
            int gr = k0 + r, gc = colBase + c;
            Bs[r][c] = (gr < K && gc < N) ? B[(size_t)gr * N + gc] : 0.f;
        }
        __syncthreads();
#pragma unroll
        for (int kk = 0; kk < 8; kk++) {
            float a[8], b[8];
#pragma unroll
            for (int i = 0; i < 8; i++) a[i] = As[kk][ty * 8 + i];
#pragma unroll
            for (int j = 0; j < 8; j++) b[j] = Bs[kk][tx * 8 + j];
#pragma unroll
            for (int i = 0; i < 8; i++)
#pragma unroll
                for (int j = 0; j < 8; j++) acc[i][j] = fmaf(a[i], b[j], acc[i][j]);
        }
        __syncthreads();
    }
#pragma unroll
    for (int i = 0; i < 8; i++) {
        int gr = rowBase + ty * 8 + i;
        if (gr >= M) continue;
#pragma unroll
        for (int j = 0; j < 8; j++) {
            int gc = colBase + tx * 8 + j;
            if (gc < N) C[(size_t)gr * N + gc] = acc[i][j];
        }
    }
}

// ---------------- attention coefficients ------------------------------------
__global__ void att_coef1(const float* __restrict__ a_src, const float* __restrict__ a_dst) {
    int gw = (blockIdx.x * blockDim.x + threadIdx.x) >> 5;
    int lane = threadIdx.x & 31;
    if (gw >= N_NODES) return;
    const float* row = g_h1 + (size_t)gw * D1;
    float s[4] = {0, 0, 0, 0}, d[4] = {0, 0, 0, 0};
#pragma unroll
    for (int j = 0; j < 16; j++) {
        int c = lane + 32 * j;
        float v = row[c];
        s[j >> 2] = fmaf(v, a_src[c], s[j >> 2]);
        d[j >> 2] = fmaf(v, a_dst[c], d[j >> 2]);
    }
#pragma unroll
    for (int h = 0; h < 4; h++) { s[h] = warpSum(s[h]); d[h] = warpSum(d[h]); }
    if (lane == 0) {
#pragma unroll
        for (int h = 0; h < 4; h++) {
            g_als1[gw * 4 + h] = s[h];
            g_ald1[gw * 4 + h] = d[h];
        }
    }
}

__global__ void att_coef2(const float* __restrict__ a_src, const float* __restrict__ a_dst) {
    int gw = (blockIdx.x * blockDim.x + threadIdx.x) >> 5;
    int lane = threadIdx.x & 31;
    if (gw >= N_NODES) return;
    const float* row = g_h2 + (size_t)gw * HID;
    float s = 0.f, d = 0.f;
#pragma unroll
    for (int j = 0; j < 4; j++) {
        int c = lane + 32 * j;
        float v = row[c];
        s = fmaf(v, a_src[c], s);
        d = fmaf(v, a_dst[c], d);
    }
    s = warpSum(s); d = warpSum(d);
    if (lane == 0) { g_als2[gw] = s; g_ald2[gw] = d; }
}

// ---------------- GAT layer 1: softmax + aggregate (warp per dst node) ------
__global__ __launch_bounds__(256) void gat_agg1(const float* __restrict__ b1) {
    int gw = (blockIdx.x * blockDim.x + threadIdx.x) >> 5;
    int lane = threadIdx.x & 31;
    if (gw >= N_NODES) return;
    int beg = g_offsets[gw], end = g_offsets[gw + 1];

    float ald[4];
#pragma unroll
    for (int h = 0; h < 4; h++) ald[h] = g_ald1[gw * 4 + h];

    float mx[4] = {-1e30f, -1e30f, -1e30f, -1e30f};
    for (int i = beg + lane; i < end; i += 32) {
        int s = g_src_sorted[i];
#pragma unroll
        for (int h = 0; h < 4; h++) {
            float e = lrelu(g_als1[s * 4 + h] + ald[h]);
            mx[h] = fmaxf(mx[h], e);
        }
    }
#pragma unroll
    for (int h = 0; h < 4; h++) mx[h] = warpMax(mx[h]);

    float sm[4] = {0, 0, 0, 0};
    for (int i = beg + lane; i < end; i += 32) {
        int s = g_src_sorted[i];
        float4 ex4;
        float* exv = (float*)&ex4;
#pragma unroll
        for (int h = 0; h < 4; h++) {
            float e = lrelu(g_als1[s * 4 + h] + ald[h]);
            float ex = __expf(e - mx[h]);
            exv[h] = ex;
            sm[h] += ex;
        }
        ((float4*)g_alpha1)[i] = ex4;
    }
#pragma unroll
    for (int h = 0; h < 4; h++) sm[h] = warpSum(sm[h]);
    float inv[4];
#pragma unroll
    for (int h = 0; h < 4; h++) inv[h] = 1.f / sm[h];
    __syncwarp();

    float acc[16];
#pragma unroll
    for (int j = 0; j < 16; j++) acc[j] = 0.f;
    for (int i = beg; i < end; i++) {
        int s = g_src_sorted[i];
        float4 a4 = ((const float4*)g_alpha1)[i];
        const float* hr = g_h1 + (size_t)s * D1;
#pragma unroll
        for (int j = 0; j < 16; j++) {
            float a = (j < 4) ? a4.x : (j < 8) ? a4.y : (j < 12) ? a4.z : a4.w;
            acc[j] = fmaf(a, hr[lane + 32 * j], acc[j]);
        }
    }
#pragma unroll
    for (int j = 0; j < 16; j++) {
        int c = lane + 32 * j;
        float v = acc[j] * inv[j >> 2] + b1[c];
        g_out1[(size_t)gw * D1 + c] = fmaxf(v, 0.f);
    }
}

// ---------------- GAT layer 2 ------------------------------------------------
__global__ __launch_bounds__(256) void gat_agg2(const float* __restrict__ b2) {
    int gw = (blockIdx.x * blockDim.x + threadIdx.x) >> 5;
    int lane = threadIdx.x & 31;
    if (gw >= N_NODES) return;
    int beg = g_offsets[gw], end = g_offsets[gw + 1];
    float ald = g_ald2[gw];

    float mx = -1e30f;
    for (int i = beg + lane; i < end; i += 32)
        mx = fmaxf(mx, lrelu(g_als2[g_src_sorted[i]] + ald));
    mx = warpMax(mx);

    float sm = 0.f;
    for (int i = beg + lane; i < end; i += 32) {
        float e = lrelu(g_als2[g_src_sorted[i]] + ald);
        float ex = __expf(e - mx);
        g_alpha2[i] = ex;
        sm += ex;
    }
    sm = warpSum(sm);
    float inv = 1.f / sm;
    __syncwarp();

    float acc[4] = {0, 0, 0, 0};
    for (int i = beg; i < end; i++) {
        int s = g_src_sorted[i];
        float a = g_alpha2[i];
        const float* hr = g_h2 + (size_t)s * HID;
#pragma unroll
        for (int j = 0; j < 4; j++)
            acc[j] = fmaf(a, hr[lane + 32 * j], acc[j]);
    }
#pragma unroll
    for (int j = 0; j < 4; j++) {
        int c = lane + 32 * j;
        float v = acc[j] * inv + b2[c];
        g_out2[(size_t)gw * HID + c] = fmaxf(v, 0.f);
    }
}

// ---------------- global mean pool -------------------------------------------
__global__ void pool_kernel(const int* __restrict__ batch) {
    int gw = (blockIdx.x * blockDim.x + threadIdx.x) >> 5;
    int lane = threadIdx.x & 31;
    if (gw >= N_NODES) return;
    int g = batch[gw];
#pragma unroll
    for (int j = 0; j < 4; j++) {
        int c = lane + 32 * j;
        atomicAdd(&g_pool[g * HID + c], g_out2[(size_t)gw * HID + c]);
    }
    if (lane == 0) atomicAdd(&g_cnt[g], 1);
}

// ---------------- MLP head ----------------------------------------------------
__global__ __launch_bounds__(1024) void mlp_kernel(
    const float* __restrict__ fc1_w, const float* __restrict__ fc1_b,
    const float* __restrict__ fc2_w, const float* __restrict__ fc2_b,
    float* __restrict__ out)
{
    __shared__ float pooled[NUM_GRAPHS * HID];
    __shared__ float z[NUM_GRAPHS * 64];
    int tid = threadIdx.x;
    for (int i = tid; i < NUM_GRAPHS * HID; i += blockDim.x) {
        int g = i / HID;
        float c = fmaxf((float)g_cnt[g], 1.f);
        pooled[i] = g_pool[i] / c;
    }
    __syncthreads();
    for (int i = tid; i < NUM_GRAPHS * 64; i += blockDim.x) {
        int g = i >> 6, j = i & 63;
        float acc = fc1_b[j];
        for (int k = 0; k < HID; k++)
            acc = fmaf(pooled[g * HID + k], fc1_w[k * 64 + j], acc);
        z[i] = fmaxf(acc, 0.f);
    }
    __syncthreads();
    for (int i = tid; i < NUM_GRAPHS * NUM_CLASSES; i += blockDim.x) {
        int g = i / NUM_CLASSES, c = i % NUM_CLASSES;
        float acc = fc2_b[c];
        for (int j = 0; j < 64; j++)
            acc = fmaf(z[g * 64 + j], fc2_w[j * NUM_CLASSES + c], acc);
        out[i] = acc;
    }
}

// ---------------- launch ------------------------------------------------------
extern "C" void kernel_launch(void* const* d_in, const int* in_sizes, int n_in,
                              void* d_out, int out_size) {
    const float* x       = (const float*)d_in[0];
    const int*   ei      = (const int*)  d_in[1];
    const int*   batch   = (const int*)  d_in[2];
    const float* W1      = (const float*)d_in[3];
    const float* a_src1  = (const float*)d_in[4];
    const float* a_dst1  = (const float*)d_in[5];
    const float* b1      = (const float*)d_in[6];
    const float* W2      = (const float*)d_in[7];
    const float* a_src2  = (const float*)d_in[8];
    const float* a_dst2  = (const float*)d_in[9];
    const float* b2      = (const float*)d_in[10];
    const float* fc1_w   = (const float*)d_in[11];
    const float* fc1_b   = (const float*)d_in[12];
    const float* fc2_w   = (const float*)d_in[13];
    const float* fc2_b   = (const float*)d_in[14];
    float* out = (float*)d_out;

    // Resolve scratch symbol addresses (host API, not a stream op — capture safe).
    // NOTE: __device__ symbols must NOT be passed directly from host code.
    static float* p_h1 = nullptr;
    static float* p_out1 = nullptr;
    static float* p_h2 = nullptr;
    if (!p_h1) {
        cudaGetSymbolAddress((void**)&p_h1,   g_h1);
        cudaGetSymbolAddress((void**)&p_out1, g_out1);
        cudaGetSymbolAddress((void**)&p_h2,   g_h2);
    }

    // zero scratch + build CSR sorted by dst
    zero_kernel<<<(N_NODES + 255) / 256, 256>>>();
    hist_kernel<<<(E_TOT + 255) / 256, 256>>>(ei);
    scan_kernel<<<1, 1024>>>();
    scatter_kernel<<<(E_TOT + 255) / 256, 256>>>(ei);

    // GEMM1: h1 = x @ W1   [50000 x 814] @ [814 x 512]
    {
        dim3 grid((D1 + 127) / 128, (N_NODES + 127) / 128);
        sgemm128<<<grid, 256>>>(x, W1, p_h1, N_NODES, D1, IN_CH);
    }
    att_coef1<<<(N_NODES * 32 + 255) / 256, 256>>>(a_src1, a_dst1);
    gat_agg1<<<(N_NODES * 32 + 255) / 256, 256>>>(b1);

    // GEMM2: h2 = out1 @ W2   [50000 x 512] @ [512 x 128]
    {
        dim3 grid((HID + 127) / 128, (N_NODES + 127) / 128);
        sgemm128<<<grid, 256>>>(p_out1, W2, p_h2, N_NODES, HID, D1);
    }
    att_coef2<<<(N_NODES * 32 + 255) / 256, 256>>>(a_src2, a_dst2);
    gat_agg2<<<(N_NODES * 32 + 255) / 256, 256>>>(b2);

    pool_kernel<<<(N_NODES * 32 + 255) / 256, 256>>>(batch);
    mlp_kernel<<<1, 1024>>>(fc1_w, fc1_b, fc2_w, fc2_b, out);
}

// round 4
// speedup vs baseline: 1.5316x; 1.5316x over previous
#include <cuda_runtime.h>
#include <cuda_bf16.h>
#include <cstdint>
#include <math.h>

#define N_NODES 50000
#define N_EDGES 400000
#define E_TOT   450000
#define IN_CH   814
#define KP1     832          /* 814 padded to 13*64 */
#define HID     128
#define HEADS1  4
#define D1      (HEADS1*HID) /* 512 */
#define NUM_CLASSES 46
#define NUM_GRAPHS  64
#define NEG_SLOPE   0.2f

// tcgen05 only exists on arch-specific ('a') targets.
#if defined(__CUDA_ARCH_FEAT_SM103_ALL) || defined(__CUDA_ARCH_FEAT_SM100_ALL)
#define HAS_TC 1
#else
#define HAS_TC 0
#endif

// ---------------- scratch (static device globals) ---------------------------
__device__ float g_h1[N_NODES * D1];                 // GEMM1 out (fp32)
__device__ float g_h2[N_NODES * HID];                // GEMM2 out (fp32)
__device__ float g_out2[N_NODES * HID];
__device__ __nv_bfloat16 g_xh[N_NODES * KP1];        // x split hi
__device__ __nv_bfloat16 g_xl[N_NODES * KP1];        // x split lo
__device__ __nv_bfloat16 g_o1h[N_NODES * D1];        // out1 split hi
__device__ __nv_bfloat16 g_o1l[N_NODES * D1];        // out1 split lo
__device__ __nv_bfloat16 g_b1h[D1 * KP1];            // W1^T split hi
__device__ __nv_bfloat16 g_b1l[D1 * KP1];
__device__ __nv_bfloat16 g_b2h[HID * D1];            // W2^T split hi
__device__ __nv_bfloat16 g_b2l[HID * D1];
__device__ float g_als1[N_NODES * HEADS1];
__device__ float g_ald1[N_NODES * HEADS1];
__device__ float g_als2[N_NODES];
__device__ float g_ald2[N_NODES];
__device__ int   g_counts[N_NODES];
__device__ int   g_offsets[N_NODES + 1];
__device__ int   g_cursor[N_NODES];
__device__ int   g_src_sorted[E_TOT];
__device__ float g_alpha1[E_TOT * HEADS1];
__device__ float g_alpha2[E_TOT];
__device__ float g_pool[NUM_GRAPHS * HID];
__device__ int   g_cnt[NUM_GRAPHS];

// ---------------- PTX helpers (tcgen05 path only) ----------------------------
#if HAS_TC
__device__ __forceinline__ uint32_t smem_u32(const void* p) {
    uint32_t a;
    asm("{ .reg .u64 t; cvta.to.shared.u64 t, %1; cvt.u32.u64 %0, t; }" : "=r"(a) : "l"(p));
    return a;
}
__device__ __forceinline__ uint32_t elect_one() {
    uint32_t pred;
    asm volatile("{ .reg .pred p; elect.sync _|p, 0xFFFFFFFF; selp.b32 %0, 1, 0, p; }" : "=r"(pred));
    return pred;
}
#define MBAR_INIT(a, n)  asm volatile("mbarrier.init.shared.b64 [%0], %1;" :: "r"(a), "r"((uint32_t)(n)) : "memory")
#define MBAR_WAIT(a, ph) do { \
    uint32_t _m = (a), _p = (ph), _d; \
    asm volatile("{ .reg .pred p; mbarrier.try_wait.parity.acquire.cta.shared::cta.b64 p, [%1], %2; selp.b32 %0,1,0,p; }" \
        : "=r"(_d) : "r"(_m), "r"(_p) : "memory"); \
    if (!_d) { \
        asm volatile("{ .reg .pred P1;\nWL_%=:\nmbarrier.try_wait.parity.acquire.cta.shared::cta.b64 P1, [%0], %1, 0x989680;\n@P1 bra.uni WD_%=;\nbra.uni WL_%=;\nWD_%=:\n}" \
            :: "r"(_m), "r"(_p) : "memory"); \
    } } while (0)
#define TC_ALLOC(sa, n)   asm volatile("tcgen05.alloc.cta_group::1.sync.aligned.shared::cta.b32 [%0], %1;" :: "r"(sa), "r"((uint32_t)(n)) : "memory")
#define TC_DEALLOC(t, n)  asm volatile("tcgen05.dealloc.cta_group::1.sync.aligned.b32 %0, %1;" :: "r"(t), "r"((uint32_t)(n)))
#define TC_RELINQ()       asm volatile("tcgen05.relinquish_alloc_permit.cta_group::1.sync.aligned;")
#define TC_COMMIT(a)      asm volatile("tcgen05.commit.cta_group::1.mbarrier::arrive::one.shared::cluster.b64 [%0];" :: "r"(a) : "memory")
#define TC_FENCE_AFTER()  asm volatile("tcgen05.fence::after_thread_sync;" ::: "memory")
#define TC_FENCE_BEFORE() asm volatile("tcgen05.fence::before_thread_sync;" ::: "memory")
#define TC_WAIT_LD()      asm volatile("tcgen05.wait::ld.sync.aligned;" ::: "memory")
#define FENCE_ASYNC()     asm volatile("fence.proxy.async.shared::cta;" ::: "memory")

__device__ __forceinline__ void mma_f16_ss(uint32_t d, uint64_t ad, uint64_t bd,
                                           uint32_t idesc, bool accum) {
    uint32_t en = accum ? 1u : 0u, z = 0u;
    asm volatile(
        "{ .reg .pred p; setp.ne.u32 p, %5, 0;\n\t"
        "tcgen05.mma.cta_group::1.kind::f16 [%0], %1, %2, %3, {%4,%4,%4,%4}, p; }"
        :: "r"(d), "l"(ad), "l"(bd), "r"(idesc), "r"(z), "r"(en) : "memory");
}
__device__ __forceinline__ void tmem_ld32(uint32_t* r, uint32_t addr) {
    asm volatile(
        "tcgen05.ld.sync.aligned.32x32b.x32.b32 "
        "{%0,%1,%2,%3,%4,%5,%6,%7,%8,%9,%10,%11,%12,%13,%14,%15,"
        "%16,%17,%18,%19,%20,%21,%22,%23,%24,%25,%26,%27,%28,%29,%30,%31}, [%32];"
        : "=r"(r[0]), "=r"(r[1]), "=r"(r[2]), "=r"(r[3]), "=r"(r[4]), "=r"(r[5]), "=r"(r[6]), "=r"(r[7]),
          "=r"(r[8]), "=r"(r[9]), "=r"(r[10]), "=r"(r[11]), "=r"(r[12]), "=r"(r[13]), "=r"(r[14]), "=r"(r[15]),
          "=r"(r[16]), "=r"(r[17]), "=r"(r[18]), "=r"(r[19]), "=r"(r[20]), "=r"(r[21]), "=r"(r[22]), "=r"(r[23]),
          "=r"(r[24]), "=r"(r[25]), "=r"(r[26]), "=r"(r[27]), "=r"(r[28]), "=r"(r[29]), "=r"(r[30]), "=r"(r[31])
        : "r"(addr));
}
// SW128 smem descriptor: layout=2, version=1, SBO=64, LBO=1
#define DESC_SW128(addr) ((uint64_t(2) << 61) | (uint64_t(1) << 46) | (uint64_t(64) << 32) \
                          | (uint64_t(1) << 16) | ((uint64_t)((addr) >> 4) & 0x3FFF))

__device__ __forceinline__ void load_tile(uint32_t dstBase, const __nv_bfloat16* src, int tid) {
    const uint4* p = (const uint4*)src;
#pragma unroll
    for (int i = 0; i < 8; i++) {
        uint4 v = p[i];
        uint32_t byte = tid * 128 + i * 16;
        uint32_t a = dstBase + (byte ^ ((byte >> 3) & 0x70));
        asm volatile("st.shared.v4.b32 [%0], {%1,%2,%3,%4};"
                     :: "r"(a), "r"(v.x), "r"(v.y), "r"(v.z), "r"(v.w));
    }
}
#endif // HAS_TC

// ---------------- tcgen05 bf16x3 GEMM: C[M,N] = A[M,K] @ B^T ------------------
// A tables: Ah/Al [M, kp] bf16 (kp%64==0). B tables: Bh/Bl [N, kp] bf16 (W^T).
// D = Ah*Bh + Al*Bh + Ah*Bl  via 3 K-segments. No-op when !HAS_TC.
__global__ void __launch_bounds__(128, 1)
gemm_tc(const __nv_bfloat16* __restrict__ Ah, const __nv_bfloat16* __restrict__ Al,
        const __nv_bfloat16* __restrict__ Bh, const __nv_bfloat16* __restrict__ Bl,
        float* __restrict__ C, int M, int ldc, int kp)
{
#if HAS_TC
    extern __shared__ char dsm[];
    uint32_t sb = smem_u32(dsm);
    uint32_t base = (sb + 1023) & ~1023u;
    const uint32_t TM_PTR = base;
    const uint32_t MBAR   = base + 8;
    const uint32_t AOFF0 = base + 1024, AOFF1 = AOFF0 + 16384;
    const uint32_t BOFF0 = AOFF0 + 32768, BOFF1 = AOFF0 + 49152;

    int tid = threadIdx.x, wid = tid >> 5, lane = tid & 31;
    int m0 = blockIdx.y * 128, n0 = blockIdx.x * 128;

    if (wid == 0) { TC_ALLOC(TM_PTR, 128); TC_RELINQ(); }
    if (tid == 0) MBAR_INIT(MBAR, 1);
    __syncthreads();
    uint32_t tmem;
    asm volatile("ld.shared.b32 %0, [%1];" : "=r"(tmem) : "r"(TM_PTR));

    const int nck = kp >> 6;      // 64-wide K chunks per segment
    const int NC = 3 * nck;

    int arow = m0 + tid; if (arow >= M) arow = M - 1;
    const __nv_bfloat16* aH = Ah + (size_t)arow * kp;
    const __nv_bfloat16* aL = Al + (size_t)arow * kp;
    const __nv_bfloat16* bH = Bh + (size_t)(n0 + tid) * kp;
    const __nv_bfloat16* bL = Bl + (size_t)(n0 + tid) * kp;

    const uint32_t IDESC = 0x8200490u;  // fp32 acc, bf16 a/b, N=128, M=128

    // prologue: chunk 0
    load_tile(AOFF0, aH, tid);
    load_tile(BOFF0, bH, tid);
    FENCE_ASYNC();
    __syncthreads();

    for (int c = 0; c < NC; c++) {
        int buf = c & 1;
        uint32_t aBase = buf ? AOFF1 : AOFF0;
        uint32_t bBase = buf ? BOFF1 : BOFF0;
        if (wid == 0) {
            if (elect_one()) {
                uint64_t ad = DESC_SW128(aBase);
                uint64_t bd = DESC_SW128(bBase);
#pragma unroll
                for (int k = 0; k < 4; k++)
                    mma_f16_ss(tmem, ad + 2 * k, bd + 2 * k, IDESC, !(c == 0 && k == 0));
                TC_COMMIT(MBAR);
            }
        }
        if (c + 1 < NC) {
            int cn = c + 1;
            int seg = cn / nck;
            int kc = (cn - seg * nck) << 6;
            const __nv_bfloat16* sa = (seg == 1) ? aL : aH;
            const __nv_bfloat16* sbp = (seg == 2) ? bL : bH;
            uint32_t aB2 = (buf ^ 1) ? AOFF1 : AOFF0;
            uint32_t bB2 = (buf ^ 1) ? BOFF1 : BOFF0;
            load_tile(aB2, sa + kc, tid);
            load_tile(bB2, sbp + kc, tid);
            FENCE_ASYNC();
        }
        MBAR_WAIT(MBAR, c & 1);
        __syncthreads();
    }

    TC_FENCE_AFTER();
    // epilogue: each warp reads its 32-row subpartition; 4 batches of 32 N-cols
#pragma unroll
    for (int nb = 0; nb < 4; nb++) {
        uint32_t r[32];
        tmem_ld32(r, tmem + nb * 32);
        TC_WAIT_LD();
        int row = m0 + wid * 32 + lane;
        if (row < M) {
            float4* dst = (float4*)(C + (size_t)row * ldc + n0 + nb * 32);
#pragma unroll
            for (int i = 0; i < 8; i++)
                dst[i] = make_float4(__uint_as_float(r[4 * i]), __uint_as_float(r[4 * i + 1]),
                                     __uint_as_float(r[4 * i + 2]), __uint_as_float(r[4 * i + 3]));
        }
    }
    TC_FENCE_BEFORE();
    __syncthreads();
    if (wid == 0) TC_DEALLOC(tmem, 128);
#endif
}

// ---------------- SIMT fallback GEMM (only active when !HAS_TC) ---------------
// Reconstructs fp32 A = Ah+Al, B = Bh+Bl (B stored [N, kp] = W^T).
__global__ __launch_bounds__(256) void gemm_simt(
    const __nv_bfloat16* __restrict__ Ah, const __nv_bfloat16* __restrict__ Al,
    const __nv_bfloat16* __restrict__ Bh, const __nv_bfloat16* __restrict__ Bl,
    float* __restrict__ C, int M, int ldc, int kp)
{
#if !HAS_TC
    __shared__ float As[8][128];
    __shared__ float Bs[8][128];
    int tid = threadIdx.x;
    int tx = tid & 15, ty = tid >> 4;
    int rowBase = blockIdx.y * 128;
    int colBase = blockIdx.x * 128;
    int N = gridDim.x * 128;

    float acc[8][8];
#pragma unroll
    for (int i = 0; i < 8; i++)
#pragma unroll
        for (int j = 0; j < 8; j++) acc[i][j] = 0.f;

    for (int k0 = 0; k0 < kp; k0 += 8) {
#pragma unroll
        for (int i = 0; i < 4; i++) {
            int idx = tid + 256 * i;
            int r = idx >> 3, c = idx & 7;
            int gr = rowBase + r;
            float v = 0.f;
            if (gr < M) {
                size_t o = (size_t)gr * kp + k0 + c;
                v = __bfloat162float(Ah[o]) + __bfloat162float(Al[o]);
            }
            As[c][r] = v;
        }
#pragma unroll
        for (int i = 0; i < 4; i++) {
            int idx = tid + 256 * i;
            int nl = idx >> 3, kk = idx & 7;
            int gn = colBase + nl;
            float v = 0.f;
            if (gn < N) {
                size_t o = (size_t)gn * kp + k0 + kk;
                v = __bfloat162float(Bh[o]) + __bfloat162float(Bl[o]);
            }
            Bs[kk][nl] = v;
        }
        __syncthreads();
#pragma unroll
        for (int kk = 0; kk < 8; kk++) {
            float a[8], b[8];
#pragma unroll
            for (int i = 0; i < 8; i++) a[i] = As[kk][ty * 8 + i];
#pragma unroll
            for (int j = 0; j < 8; j++) b[j] = Bs[kk][tx * 8 + j];
#pragma unroll
            for (int i = 0; i < 8; i++)
#pragma unroll
                for (int j = 0; j < 8; j++) acc[i][j] = fmaf(a[i], b[j], acc[i][j]);
        }
        __syncthreads();
    }
#pragma unroll
    for (int i = 0; i < 8; i++) {
        int gr = rowBase + ty * 8 + i;
        if (gr >= M) continue;
#pragma unroll
        for (int j = 0; j < 8; j++) {
            int gc = colBase + tx * 8 + j;
            C[(size_t)gr * ldc + gc] = acc[i][j];
        }
    }
#endif
}

// ---------------- conversions ------------------------------------------------
__global__ void cvt_w_kernel(const float* __restrict__ W1, const float* __restrict__ W2) {
    int idx = blockIdx.x * blockDim.x + threadIdx.x;
    const int n1 = D1 * KP1;
    if (idx < n1) {
        int n = idx / KP1, k = idx - n * KP1;
        float v = (k < IN_CH) ? W1[(size_t)k * D1 + n] : 0.f;
        __nv_bfloat16 hi = __float2bfloat16(v);
        g_b1h[idx] = hi;
        g_b1l[idx] = __float2bfloat16(v - __bfloat162float(hi));
        return;
    }
    int j = idx - n1;
    if (j < HID * D1) {
        int n = j / D1, k = j - n * D1;
        float v = W2[(size_t)k * HID + n];
        __nv_bfloat16 hi = __float2bfloat16(v);
        g_b2h[j] = hi;
        g_b2l[j] = __float2bfloat16(v - __bfloat162float(hi));
    }
}

__global__ void cvt_x_kernel(const float* __restrict__ x) {
    int idx = blockIdx.x * blockDim.x + threadIdx.x;
    if (idx >= N_NODES * KP1) return;
    int row = idx / KP1, k = idx - row * KP1;
    float v = (k < IN_CH) ? x[(size_t)row * IN_CH + k] : 0.f;
    __nv_bfloat16 hi = __float2bfloat16(v);
    g_xh[idx] = hi;
    g_xl[idx] = __float2bfloat16(v - __bfloat162float(hi));
}

// ---------------- misc helpers -----------------------------------------------
__device__ __forceinline__ float warpMax(float v) {
#pragma unroll
    for (int o = 16; o > 0; o >>= 1) v = fmaxf(v, __shfl_xor_sync(0xffffffffu, v, o));
    return v;
}
__device__ __forceinline__ float warpSum(float v) {
#pragma unroll
    for (int o = 16; o > 0; o >>= 1) v += __shfl_xor_sync(0xffffffffu, v, o);
    return v;
}
__device__ __forceinline__ float lrelu(float x) { return x > 0.f ? x : NEG_SLOPE * x; }

// ---------------- zero scratch -----------------------------------------------
__global__ void zero_kernel() {
    int i = blockIdx.x * blockDim.x + threadIdx.x;
    if (i < N_NODES) g_counts[i] = 0;
    if (i < NUM_GRAPHS * HID) g_pool[i] = 0.f;
    if (i < NUM_GRAPHS) g_cnt[i] = 0;
}

// ---------------- CSR build (dst-sorted) ---------------------------------------
__global__ void hist_kernel(const int* __restrict__ ei) {
    int e = blockIdx.x * blockDim.x + threadIdx.x;
    if (e >= E_TOT) return;
    int dst = (e < N_EDGES) ? ei[N_EDGES + e] : (e - N_EDGES);
    atomicAdd(&g_counts[dst], 1);
}

__global__ void scan_kernel() {
    __shared__ int sh[1024];
    const int n = N_NODES;
    const int chunk = (n + 1023) / 1024;
    int tid = threadIdx.x;
    int b = tid * chunk;
    int e = b + chunk; if (e > n) e = n; if (b > n) b = n;
    int s = 0;
    for (int i = b; i < e; i++) s += g_counts[i];
    sh[tid] = s;
    __syncthreads();
    for (int o = 1; o < 1024; o <<= 1) {
        int v = 0;
        if (tid >= o) v = sh[tid - o];
        __syncthreads();
        if (tid >= o) sh[tid] += v;
        __syncthreads();
    }
    int run = (tid == 0) ? 0 : sh[tid - 1];
    for (int i = b; i < e; i++) {
        g_offsets[i] = run;
        g_cursor[i]  = run;
        run += g_counts[i];
    }
    if (tid == 1023) g_offsets[n] = sh[1023];
}

__global__ void scatter_kernel(const int* __restrict__ ei) {
    int e = blockIdx.x * blockDim.x + threadIdx.x;
    if (e >= E_TOT) return;
    int src, dst;
    if (e < N_EDGES) { src = ei[e]; dst = ei[N_EDGES + e]; }
    else             { src = e - N_EDGES; dst = src; }
    int pos = atomicAdd(&g_cursor[dst], 1);
    g_src_sorted[pos] = src;
}

// ---------------- attention coefficients ---------------------------------------
__global__ void att_coef1(const float* __restrict__ a_src, const float* __restrict__ a_dst) {
    int gw = (blockIdx.x * blockDim.x + threadIdx.x) >> 5;
    int lane = threadIdx.x & 31;
    if (gw >= N_NODES) return;
    const float* row = g_h1 + (size_t)gw * D1;
    float s[4] = {0, 0, 0, 0}, d[4] = {0, 0, 0, 0};
#pragma unroll
    for (int j = 0; j < 16; j++) {
        int c = lane + 32 * j;
        float v = row[c];
        s[j >> 2] = fmaf(v, a_src[c], s[j >> 2]);
        d[j >> 2] = fmaf(v, a_dst[c], d[j >> 2]);
    }
#pragma unroll
    for (int h = 0; h < 4; h++) { s[h] = warpSum(s[h]); d[h] = warpSum(d[h]); }
    if (lane == 0) {
#pragma unroll
        for (int h = 0; h < 4; h++) {
            g_als1[gw * 4 + h] = s[h];
            g_ald1[gw * 4 + h] = d[h];
        }
    }
}

__global__ void att_coef2(const float* __restrict__ a_src, const float* __restrict__ a_dst) {
    int gw = (blockIdx.x * blockDim.x + threadIdx.x) >> 5;
    int lane = threadIdx.x & 31;
    if (gw >= N_NODES) return;
    const float* row = g_h2 + (size_t)gw * HID;
    float s = 0.f, d = 0.f;
#pragma unroll
    for (int j = 0; j < 4; j++) {
        int c = lane + 32 * j;
        float v = row[c];
        s = fmaf(v, a_src[c], s);
        d = fmaf(v, a_dst[c], d);
    }
    s = warpSum(s); d = warpSum(d);
    if (lane == 0) { g_als2[gw] = s; g_ald2[gw] = d; }
}

// ---------------- GAT layer 1: softmax + aggregate (warp per dst node) ---------
// epilogue writes bf16 hi/lo split of relu(out) for GEMM2.
__global__ __launch_bounds__(256) void gat_agg1(const float* __restrict__ b1) {
    int gw = (blockIdx.x * blockDim.x + threadIdx.x) >> 5;
    int lane = threadIdx.x & 31;
    if (gw >= N_NODES) return;
    int beg = g_offsets[gw], end = g_offsets[gw + 1];

    float ald[4];
#pragma unroll
    for (int h = 0; h < 4; h++) ald[h] = g_ald1[gw * 4 + h];

    float mx[4] = {-1e30f, -1e30f, -1e30f, -1e30f};
    for (int i = beg + lane; i < end; i += 32) {
        int s = g_src_sorted[i];
#pragma unroll
        for (int h = 0; h < 4; h++) {
            float e = lrelu(g_als1[s * 4 + h] + ald[h]);
            mx[h] = fmaxf(mx[h], e);
        }
    }
#pragma unroll
    for (int h = 0; h < 4; h++) mx[h] = warpMax(mx[h]);

    float sm[4] = {0, 0, 0, 0};
    for (int i = beg + lane; i < end; i += 32) {
        int s = g_src_sorted[i];
        float4 ex4;
        float* exv = (float*)&ex4;
#pragma unroll
        for (int h = 0; h < 4; h++) {
            float e = lrelu(g_als1[s * 4 + h] + ald[h]);
            float ex = __expf(e - mx[h]);
            exv[h] = ex;
            sm[h] += ex;
        }
        ((float4*)g_alpha1)[i] = ex4;
    }
#pragma unroll
    for (int h = 0; h < 4; h++) sm[h] = warpSum(sm[h]);
    float inv[4];
#pragma unroll
    for (int h = 0; h < 4; h++) inv[h] = 1.f / sm[h];
    __syncwarp();

    float acc[16];
#pragma unroll
    for (int j = 0; j < 16; j++) acc[j] = 0.f;
    for (int i = beg; i < end; i++) {
        int s = g_src_sorted[i];
        float4 a4 = ((const float4*)g_alpha1)[i];
        const float* hr = g_h1 + (size_t)s * D1;
#pragma unroll
        for (int j = 0; j < 16; j++) {
            float a = (j < 4) ? a4.x : (j < 8) ? a4.y : (j < 12) ? a4.z : a4.w;
            acc[j] = fmaf(a, hr[lane + 32 * j], acc[j]);
        }
    }
#pragma unroll
    for (int j = 0; j < 16; j++) {
        int c = lane + 32 * j;
        float v = fmaxf(acc[j] * inv[j >> 2] + b1[c], 0.f);
        __nv_bfloat16 hi = __float2bfloat16(v);
        g_o1h[(size_t)gw * D1 + c] = hi;
        g_o1l[(size_t)gw * D1 + c] = __float2bfloat16(v - __bfloat162float(hi));
    }
}

// ---------------- GAT layer 2 ----------------------------------------------------
__global__ __launch_bounds__(256) void gat_agg2(const float* __restrict__ b2) {
    int gw = (blockIdx.x * blockDim.x + threadIdx.x) >> 5;
    int lane = threadIdx.x & 31;
    if (gw >= N_NODES) return;
    int beg = g_offsets[gw], end = g_offsets[gw + 1];
    float ald = g_ald2[gw];

    float mx = -1e30f;
    for (int i = beg + lane; i < end; i += 32)
        mx = fmaxf(mx, lrelu(g_als2[g_src_sorted[i]] + ald));
    mx = warpMax(mx);

    float sm = 0.f;
    for (int i = beg + lane; i < end; i += 32) {
        float e = lrelu(g_als2[g_src_sorted[i]] + ald);
        float ex = __expf(e - mx);
        g_alpha2[i] = ex;
        sm += ex;
    }
    sm = warpSum(sm);
    float inv = 1.f / sm;
    __syncwarp();

    float acc[4] = {0, 0, 0, 0};
    for (int i = beg; i < end; i++) {
        int s = g_src_sorted[i];
        float a = g_alpha2[i];
        const float* hr = g_h2 + (size_t)s * HID;
#pragma unroll
        for (int j = 0; j < 4; j++)
            acc[j] = fmaf(a, hr[lane + 32 * j], acc[j]);
    }
#pragma unroll
    for (int j = 0; j < 4; j++) {
        int c = lane + 32 * j;
        float v = acc[j] * inv + b2[c];
        g_out2[(size_t)gw * HID + c] = fmaxf(v, 0.f);
    }
}

// ---------------- global mean pool ------------------------------------------------
__global__ void pool_kernel(const int* __restrict__ batch) {
    int gw = (blockIdx.x * blockDim.x + threadIdx.x) >> 5;
    int lane = threadIdx.x & 31;
    if (gw >= N_NODES) return;
    int g = batch[gw];
#pragma unroll
    for (int j = 0; j < 4; j++) {
        int c = lane + 32 * j;
        atomicAdd(&g_pool[g * HID + c], g_out2[(size_t)gw * HID + c]);
    }
    if (lane == 0) atomicAdd(&g_cnt[g], 1);
}

// ---------------- MLP head -----------------------------------------------------------
__global__ __launch_bounds__(1024) void mlp_kernel(
    const float* __restrict__ fc1_w, const float* __restrict__ fc1_b,
    const float* __restrict__ fc2_w, const float* __restrict__ fc2_b,
    float* __restrict__ out)
{
    __shared__ float pooled[NUM_GRAPHS * HID];
    __shared__ float z[NUM_GRAPHS * 64];
    int tid = threadIdx.x;
    for (int i = tid; i < NUM_GRAPHS * HID; i += blockDim.x) {
        int g = i / HID;
        float c = fmaxf((float)g_cnt[g], 1.f);
        pooled[i] = g_pool[i] / c;
    }
    __syncthreads();
    for (int i = tid; i < NUM_GRAPHS * 64; i += blockDim.x) {
        int g = i >> 6, j = i & 63;
        float acc = fc1_b[j];
        for (int k = 0; k < HID; k++)
            acc = fmaf(pooled[g * HID + k], fc1_w[k * 64 + j], acc);
        z[i] = fmaxf(acc, 0.f);
    }
    __syncthreads();
    for (int i = tid; i < NUM_GRAPHS * NUM_CLASSES; i += blockDim.x) {
        int g = i / NUM_CLASSES, c = i % NUM_CLASSES;
        float acc = fc2_b[c];
        for (int j = 0; j < 64; j++)
            acc = fmaf(z[g * 64 + j], fc2_w[j * NUM_CLASSES + c], acc);
        out[i] = acc;
    }
}

// ---------------- launch ----------------------------------------------------------------
extern "C" void kernel_launch(void* const* d_in, const int* in_sizes, int n_in,
                              void* d_out, int out_size) {
    const float* x       = (const float*)d_in[0];
    const int*   ei      = (const int*)  d_in[1];
    const int*   batch   = (const int*)  d_in[2];
    const float* W1      = (const float*)d_in[3];
    const float* a_src1  = (const float*)d_in[4];
    const float* a_dst1  = (const float*)d_in[5];
    const float* b1      = (const float*)d_in[6];
    const float* W2      = (const float*)d_in[7];
    const float* a_src2  = (const float*)d_in[8];
    const float* a_dst2  = (const float*)d_in[9];
    const float* b2      = (const float*)d_in[10];
    const float* fc1_w   = (const float*)d_in[11];
    const float* fc1_b   = (const float*)d_in[12];
    const float* fc2_w   = (const float*)d_in[13];
    const float* fc2_b   = (const float*)d_in[14];
    float* out = (float*)d_out;

    // resolve scratch symbol addresses once (host API, capture-safe)
    static float* p_h1 = nullptr;
    static float* p_h2 = nullptr;
    static __nv_bfloat16 *p_xh, *p_xl, *p_o1h, *p_o1l, *p_b1h, *p_b1l, *p_b2h, *p_b2l;
    static bool inited = false;
    if (!inited) {
        cudaGetSymbolAddress((void**)&p_h1,  g_h1);
        cudaGetSymbolAddress((void**)&p_h2,  g_h2);
        cudaGetSymbolAddress((void**)&p_xh,  g_xh);
        cudaGetSymbolAddress((void**)&p_xl,  g_xl);
        cudaGetSymbolAddress((void**)&p_o1h, g_o1h);
        cudaGetSymbolAddress((void**)&p_o1l, g_o1l);
        cudaGetSymbolAddress((void**)&p_b1h, g_b1h);
        cudaGetSymbolAddress((void**)&p_b1l, g_b1l);
        cudaGetSymbolAddress((void**)&p_b2h, g_b2h);
        cudaGetSymbolAddress((void**)&p_b2l, g_b2l);
        cudaFuncSetAttribute(gemm_tc, cudaFuncAttributeMaxDynamicSharedMemorySize, 67584);
        inited = true;
    }

    // conversions + CSR prep
    cvt_w_kernel<<<(D1 * KP1 + HID * D1 + 255) / 256, 256>>>(W1, W2);
    cvt_x_kernel<<<(N_NODES * KP1 + 255) / 256, 256>>>(x);
    zero_kernel<<<(N_NODES + 255) / 256, 256>>>();
    hist_kernel<<<(E_TOT + 255) / 256, 256>>>(ei);
    scan_kernel<<<1, 1024>>>();

    // GEMM1: h1 = x @ W1  [50000x814]@[814x512] — tc or simt (one is a no-op)
    {
        dim3 grid(D1 / 128, (N_NODES + 127) / 128);
        gemm_tc  <<<grid, 128, 67584>>>(p_xh, p_xl, p_b1h, p_b1l, p_h1, N_NODES, D1, KP1);
        gemm_simt<<<grid, 256>>>       (p_xh, p_xl, p_b1h, p_b1l, p_h1, N_NODES, D1, KP1);
    }

    scatter_kernel<<<(E_TOT + 255) / 256, 256>>>(ei);
    att_coef1<<<(N_NODES * 32 + 255) / 256, 256>>>(a_src1, a_dst1);
    gat_agg1<<<(N_NODES * 32 + 255) / 256, 256>>>(b1);

    // GEMM2: h2 = out1 @ W2  [50000x512]@[512x128]
    {
        dim3 grid(HID / 128, (N_NODES + 127) / 128);
        gemm_tc  <<<grid, 128, 67584>>>(p_o1h, p_o1l, p_b2h, p_b2l, p_h2, N_NODES, HID, D1);
        gemm_simt<<<grid, 256>>>       (p_o1h, p_o1l, p_b2h, p_b2l, p_h2, N_NODES, HID, D1);
    }
    att_coef2<<<(N_NODES * 32 + 255) / 256, 256>>>(a_src2, a_dst2);
    gat_agg2<<<(N_NODES * 32 + 255) / 256, 256>>>(b2);

    pool_kernel<<<(N_NODES * 32 + 255) / 256, 256>>>(batch);
    mlp_kernel<<<1, 1024>>>(fc1_w, fc1_b, fc2_w, fc2_b, out);
}